// round 16
// baseline (speedup 1.0000x reference)
#include <cuda_runtime.h>
#include <math.h>
#include <stdint.h>

#define NB 16
#define C_ 256

__device__ float g_qkv  [(size_t)NB*512*1024];
__device__ float g_qkT  [(size_t)64*1024*64];
__device__ float g_xT   [(size_t)NB*1024*256];
__device__ float g_attoT[(size_t)NB*1024*256];
__device__ float g_xnew [(size_t)NB*256*1024];
__device__ float g_xnewT[(size_t)NB*1024*256];
__device__ float g_pin  [(size_t)NB*1024*1024];
__device__ float g_hidT [(size_t)NB*1024*512];
__device__ float g_yout [(size_t)NB*256*1024];
__device__ float g_g    [C_*64];

__device__ __forceinline__ uint32_t smem_u32(const void* p){
    uint32_t a;
    asm("{ .reg .u64 t; cvta.to.shared.u64 t, %1; cvt.u32.u64 %0, t; }" : "=r"(a) : "l"(p));
    return a;
}
__device__ __forceinline__ void cpasync16(uint32_t s, const void* g){
    asm volatile("cp.async.ca.shared.global [%0], [%1], 16;" :: "r"(s), "l"(g));
}
__device__ __forceinline__ float ex2(float x){
    float r; asm("ex2.approx.f32 %0, %1;" : "=f"(r) : "f"(x)); return r;
}
__device__ __forceinline__ void mma8(float* d, const uint32_t* a, uint32_t b0, uint32_t b1){
    asm volatile("mma.sync.aligned.m16n8k8.row.col.f32.tf32.tf32.f32 "
        "{%0,%1,%2,%3}, {%4,%5,%6,%7}, {%8,%9}, {%0,%1,%2,%3};"
        : "+f"(d[0]), "+f"(d[1]), "+f"(d[2]), "+f"(d[3])
        : "r"(a[0]), "r"(a[1]), "r"(a[2]), "r"(a[3]), "r"(b0), "r"(b1));
}

// ============ conv1x1 GEMM (R10), cp.async 2-stage, dual write ============
// cmVOnly=1 (qkv): write only V rows channel-major, with token-pair permutation
// perm8(j) = j<4 ? 2j : 2j-7  applied within each 8-token group.
#define GEMM_SMEM 73728
__global__ void __launch_bounds__(256, 2) gemm_mma(
    const float* __restrict__ A, int lda,
    const float* __restrict__ B, int ldb, size_t bZs,
    float* __restrict__ O, size_t oZs, int K,
    const float* __restrict__ sc, const float* __restrict__ bi,
    const float* __restrict__ res,
    float* __restrict__ tokO, int tokMode, size_t tZs, int cmVOnly)
{
    extern __shared__ float smem[];
    const int tid = threadIdx.x, wid = tid >> 5, lane = tid & 31;
    const int m0 = blockIdx.y*128, n0 = blockIdx.x*128, z = blockIdx.z;
    const float* Bp = B + (size_t)z * bZs;
    const int wm = (wid & 3) * 32, wn = (wid >> 2) * 64;
    const int grp = lane >> 2, qid = lane & 3;
    const uint32_t sb = smem_u32(smem);

    float acc[2][8][4];
    #pragma unroll
    for (int mt = 0; mt < 2; mt++)
    #pragma unroll
        for (int nt = 0; nt < 8; nt++)
        #pragma unroll
            for (int r = 0; r < 4; r++) acc[mt][nt][r] = 0.f;

    const int nkc = K >> 5;
    auto issue = [&](int i, int st){
        int k0 = i << 5;
        uint32_t abase = sb + st*36864u;
        uint32_t bbase = abase + 18432u;
        #pragma unroll
        for (int idx = tid; idx < 1024; idx += 256) {
            int r = idx >> 3, c4 = (idx & 7) * 4;
            cpasync16(abase + (uint32_t)(r*36 + c4)*4u, A + (size_t)(m0+r)*lda + k0 + c4);
            cpasync16(bbase + (uint32_t)(r*36 + c4)*4u, Bp + (size_t)(n0+r)*ldb + k0 + c4);
        }
        asm volatile("cp.async.commit_group;" ::: "memory");
    };

    issue(0, 0);
    for (int i = 0; i < nkc; i++) {
        if (i + 1 < nkc) { issue(i+1, (i+1)&1); }
        if (i + 1 < nkc) asm volatile("cp.async.wait_group 1;" ::: "memory");
        else             asm volatile("cp.async.wait_group 0;" ::: "memory");
        __syncthreads();
        const uint32_t* As = (const uint32_t*)(smem + (i&1)*9216);
        const uint32_t* Bs = As + 4608;
        #pragma unroll
        for (int ks = 0; ks < 4; ks++) {
            int kk = ks * 8;
            uint32_t a[2][4];
            #pragma unroll
            for (int mt = 0; mt < 2; mt++) {
                int r = wm + mt*16 + grp;
                a[mt][0] = As[r*36 + kk + qid];
                a[mt][1] = As[(r+8)*36 + kk + qid];
                a[mt][2] = As[r*36 + kk + qid + 4];
                a[mt][3] = As[(r+8)*36 + kk + qid + 4];
            }
            #pragma unroll
            for (int nt = 0; nt < 8; nt++) {
                int n = wn + nt*8 + grp;
                uint32_t b0 = Bs[n*36 + kk + qid];
                uint32_t b1 = Bs[n*36 + kk + qid + 4];
                mma8(acc[0][nt], a[0], b0, b1);
                mma8(acc[1][nt], a[1], b0, b1);
            }
        }
        __syncthreads();
    }

    #pragma unroll
    for (int mt = 0; mt < 2; mt++) {
        #pragma unroll
        for (int half = 0; half < 2; half++) {
            int mg = m0 + wm + mt*16 + grp + half*8;
            float s1 = sc ? sc[mg] : 1.f;
            float b1 = sc ? bi[mg] : 0.f;
            const float* rb = res ? res + (size_t)z*oZs + (size_t)mg*1024 + n0 + wn : nullptr;
            #pragma unroll
            for (int nt = 0; nt < 8; nt++) {
                int c = nt*8 + 2*qid;
                float vx = acc[mt][nt][half*2]   * s1 + b1;
                float vy = acc[mt][nt][half*2+1] * s1 + b1;
                if (rb) { float2 rv = *(const float2*)(rb + c); vx += rv.x; vy += rv.y; }
                acc[mt][nt][half*2]   = vx;
                acc[mt][nt][half*2+1] = vy;
            }
        }
    }
    if (!cmVOnly) {
        #pragma unroll
        for (int mt = 0; mt < 2; mt++) {
            #pragma unroll
            for (int half = 0; half < 2; half++) {
                int mg = m0 + wm + mt*16 + grp + half*8;
                float* ob = O + (size_t)z*oZs + (size_t)mg*1024 + n0 + wn;
                #pragma unroll
                for (int nt = 0; nt < 8; nt++) {
                    int c = nt*8 + 2*qid;
                    float2 v; v.x = acc[mt][nt][half*2]; v.y = acc[mt][nt][half*2+1];
                    *(float2*)(ob + c) = v;
                }
            }
        }
    } else if (wm >= 64) {
        // V rows only, token-permuted columns: j0=2*qid, j1=2*qid+1
        const int p0 = (qid < 2) ? 4*qid     : 4*qid - 7;
        const int p1 = (qid < 2) ? 4*qid + 2 : 4*qid - 5;
        #pragma unroll
        for (int mt = 0; mt < 2; mt++) {
            #pragma unroll
            for (int half = 0; half < 2; half++) {
                int mg = m0 + wm + mt*16 + grp + half*8;
                float* ob = O + (size_t)z*oZs + (size_t)mg*1024 + n0 + wn;
                #pragma unroll
                for (int nt = 0; nt < 8; nt++) {
                    int base = nt*8;
                    ob[base + p0] = acc[mt][nt][half*2];
                    ob[base + p1] = acc[mt][nt][half*2+1];
                }
            }
        }
    }
    if (tokMode) {
        const int tS = (tokMode == 2) ? 68 : 132;
        float* Ts = smem;
        for (int nh = 0; nh < 2; nh++) {
            if ((wid >> 2) == nh && (tokMode == 1 || wm < 64)) {
                #pragma unroll
                for (int mt = 0; mt < 2; mt++)
                #pragma unroll
                    for (int hh = 0; hh < 2; hh++) {
                        int ml = wm + mt*16 + grp + hh*8;
                        #pragma unroll
                        for (int nt = 0; nt < 8; nt++) {
                            int r = nt*8 + 2*qid;
                            Ts[r*tS + ml]     = acc[mt][nt][hh*2];
                            Ts[(r+1)*tS + ml] = acc[mt][nt][hh*2+1];
                        }
                    }
            }
            __syncthreads();
            if (tokMode == 1) {
                float* dst = tokO + (size_t)z*tZs + (size_t)(n0 + nh*64)*256 + m0;
                #pragma unroll
                for (int idx = tid; idx < 2048; idx += 256) {
                    int r = idx >> 5, c4 = (idx & 31) * 4;
                    float4 v = *(float4*)&Ts[r*tS + c4];
                    *(float4*)(dst + (size_t)r*256 + c4) = v;
                }
            } else {
                float* dst = tokO + ((size_t)(z*4 + (m0 >> 7))*1024 + n0 + nh*64)*64;
                #pragma unroll
                for (int idx = tid; idx < 1024; idx += 256) {
                    int r = idx >> 4, c4 = (idx & 15) * 4;
                    float4 v = *(float4*)&Ts[r*tS + c4];
                    *(float4*)(dst + r*64 + c4) = v;
                }
            }
            __syncthreads();
        }
    }
}

// ============ 32x32 tiled transpose (input x only) ============
__global__ void transpose_kernel(const float* __restrict__ src, float* __restrict__ dst,
                                 size_t sStr, size_t dStr, int R, int C)
{
    __shared__ float t[32][33];
    const float* s = src + (size_t)blockIdx.z * sStr;
    float* d = dst + (size_t)blockIdx.z * dStr;
    int c0 = blockIdx.x*32, r0 = blockIdx.y*32;
    int tx = threadIdx.x, ty = threadIdx.y;
    #pragma unroll
    for (int k = 0; k < 32; k += 8)
        t[ty+k][tx] = s[(size_t)(r0+ty+k)*C + c0+tx];
    __syncthreads();
    #pragma unroll
    for (int k = 0; k < 32; k += 8)
        d[(size_t)(c0+ty+k)*R + r0+tx] = t[tx][ty+k];
}

// ============ flash v5: paired-V LDS.64, Q in regs, ex2 softmax, PE ========
#define FA_SMEM 104448
__global__ void __launch_bounds__(256, 2) flash_kernel(
    const float* __restrict__ qkT, const float* __restrict__ qkv,
    const float* __restrict__ pe_w, const float* __restrict__ pe_s,
    const float* __restrict__ pe_b,
    float* __restrict__ attoT)
{
    extern __shared__ float sm[];
    const int tid = threadIdx.x, wid = tid >> 5, lane = tid & 31;
    const int grp = lane >> 2, qid = lane & 3;
    const int lanebase = lane & ~3, odd = qid & 1;
    const int src1 = lanebase + (qid >> 1), src2 = src1 + 2;
    const int m0 = blockIdx.x * 128, bh = blockIdx.y;
    const int b = bh >> 2, h = bh & 3;
    const int wq = wid * 16;
    const float* qbase = qkT + ((size_t)bh*1024 + m0)*64;
    const float* vbase = qkv + (size_t)b*524288 + (size_t)(h*128+64)*1024;
    const uint32_t sb = smem_u32(sm);
    const uint32_t koff = 4608u*4u, voff = 9216u*4u, vstr = 8448u*4u;
    const float cs2 = 0.17677669529663687f * 1.4426950408889634f;

    {
        const float* kb0 = qkT + ((size_t)bh*1024)*64 + 32;
        #pragma unroll
        for (int idx = tid; idx < 1024; idx += 256) {
            int r = idx >> 3, c4 = (idx & 7) * 4;
            cpasync16(sb + (uint32_t)(r*36 + c4)*4u, qbase + r*64 + c4);
            cpasync16(sb + koff + (uint32_t)(r*36 + c4)*4u, kb0 + r*64 + c4);
        }
        #pragma unroll
        for (int idx = tid; idx < 2048; idx += 256) {
            int dd = idx >> 5, c4 = (idx & 31) * 4;
            cpasync16(sb + voff + (uint32_t)(dd*132 + c4)*4u, vbase + (size_t)dd*1024 + c4);
        }
        asm volatile("cp.async.commit_group;" ::: "memory");
    }

    float m_i[2] = {-1e30f, -1e30f};
    float l_i[2] = {0.f, 0.f};
    float ao[8][4];
    #pragma unroll
    for (int dt = 0; dt < 8; dt++) { ao[dt][0]=0; ao[dt][1]=0; ao[dt][2]=0; ao[dt][3]=0; }

    const uint32_t* Qu = (const uint32_t*)sm;
    const uint32_t* Ku = (const uint32_t*)(sm + 4608);

    asm volatile("cp.async.wait_group 0;" ::: "memory");
    __syncthreads();
    uint32_t qa[4][4];
    #pragma unroll
    for (int ks = 0; ks < 4; ks++) {
        int kk = ks * 8;
        qa[ks][0] = Qu[(wq+grp)*36 + kk + qid];
        qa[ks][1] = Qu[(wq+grp+8)*36 + kk + qid];
        qa[ks][2] = Qu[(wq+grp)*36 + kk + qid + 4];
        qa[ks][3] = Qu[(wq+grp+8)*36 + kk + qid + 4];
    }

    for (int kc = 0; kc < 8; kc++) {
        asm volatile("cp.async.wait_group 0;" ::: "memory");
        __syncthreads();
        const uint32_t* Vu = (const uint32_t*)(sm + 9216 + (kc & 1)*8448);

        #pragma unroll
        for (int half = 0; half < 2; half++) {
            float sacc[8][4];
            #pragma unroll
            for (int nt = 0; nt < 8; nt++) { sacc[nt][0]=0; sacc[nt][1]=0; sacc[nt][2]=0; sacc[nt][3]=0; }
            #pragma unroll
            for (int ks = 0; ks < 4; ks++) {
                int kk = ks * 8;
                #pragma unroll
                for (int nt = 0; nt < 8; nt++) {
                    int n = half*64 + nt*8 + grp;
                    uint32_t b0 = Ku[n*36 + kk + qid];
                    uint32_t b1 = Ku[n*36 + kk + qid + 4];
                    mma8(sacc[nt], qa[ks], b0, b1);
                }
            }
            if (half == 1) {
                __syncthreads();
                if (kc < 7) {
                    const float* kbn = qkT + ((size_t)bh*1024 + (kc+1)*128)*64 + 32;
                    const float* vbn = vbase + (kc+1)*128;
                    uint32_t vdst = sb + voff + (uint32_t)((kc+1)&1)*vstr;
                    #pragma unroll
                    for (int idx = tid; idx < 1024; idx += 256) {
                        int r = idx >> 3, c4 = (idx & 7) * 4;
                        cpasync16(sb + koff + (uint32_t)(r*36 + c4)*4u, kbn + r*64 + c4);
                    }
                    #pragma unroll
                    for (int idx = tid; idx < 2048; idx += 256) {
                        int dd = idx >> 5, c4 = (idx & 31) * 4;
                        cpasync16(vdst + (uint32_t)(dd*132 + c4)*4u, vbn + (size_t)dd*1024 + c4);
                    }
                    asm volatile("cp.async.commit_group;" ::: "memory");
                }
            }
            float mx0 = -1e30f, mx1 = -1e30f;
            #pragma unroll
            for (int nt = 0; nt < 8; nt++) {
                mx0 = fmaxf(mx0, fmaxf(sacc[nt][0], sacc[nt][1]));
                mx1 = fmaxf(mx1, fmaxf(sacc[nt][2], sacc[nt][3]));
            }
            mx0 = fmaxf(mx0, __shfl_xor_sync(0xffffffffu, mx0, 1));
            mx0 = fmaxf(mx0, __shfl_xor_sync(0xffffffffu, mx0, 2));
            mx1 = fmaxf(mx1, __shfl_xor_sync(0xffffffffu, mx1, 1));
            mx1 = fmaxf(mx1, __shfl_xor_sync(0xffffffffu, mx1, 2));
            float mn0 = fmaxf(m_i[0], mx0), mn1 = fmaxf(m_i[1], mx1);
            float mb0 = -mn0 * cs2, mb1 = -mn1 * cs2;
            float s0 = 0.f, s1 = 0.f;
            #pragma unroll
            for (int nt = 0; nt < 8; nt++) {
                sacc[nt][0] = ex2(fmaf(sacc[nt][0], cs2, mb0));
                sacc[nt][1] = ex2(fmaf(sacc[nt][1], cs2, mb0));
                sacc[nt][2] = ex2(fmaf(sacc[nt][2], cs2, mb1));
                sacc[nt][3] = ex2(fmaf(sacc[nt][3], cs2, mb1));
                s0 += sacc[nt][0] + sacc[nt][1];
                s1 += sacc[nt][2] + sacc[nt][3];
            }
            s0 += __shfl_xor_sync(0xffffffffu, s0, 1);
            s0 += __shfl_xor_sync(0xffffffffu, s0, 2);
            s1 += __shfl_xor_sync(0xffffffffu, s1, 1);
            s1 += __shfl_xor_sync(0xffffffffu, s1, 2);
            float al0 = ex2((m_i[0] - mn0) * cs2), al1 = ex2((m_i[1] - mn1) * cs2);
            l_i[0] = l_i[0]*al0 + s0; l_i[1] = l_i[1]*al1 + s1;
            m_i[0] = mn0; m_i[1] = mn1;
            #pragma unroll
            for (int dt = 0; dt < 8; dt++) {
                ao[dt][0] *= al0; ao[dt][1] *= al0;
                ao[dt][2] *= al1; ao[dt][3] *= al1;
            }
            #pragma unroll
            for (int ks2 = 0; ks2 < 8; ks2++) {
                float p00 = __shfl_sync(0xffffffffu, sacc[ks2][0], src1);
                float p01 = __shfl_sync(0xffffffffu, sacc[ks2][1], src1);
                float p10 = __shfl_sync(0xffffffffu, sacc[ks2][2], src1);
                float p11 = __shfl_sync(0xffffffffu, sacc[ks2][3], src1);
                float q00 = __shfl_sync(0xffffffffu, sacc[ks2][0], src2);
                float q01 = __shfl_sync(0xffffffffu, sacc[ks2][1], src2);
                float q10 = __shfl_sync(0xffffffffu, sacc[ks2][2], src2);
                float q11 = __shfl_sync(0xffffffffu, sacc[ks2][3], src2);
                uint32_t a[4];
                a[0] = __float_as_uint(odd ? p01 : p00);
                a[1] = __float_as_uint(odd ? p11 : p10);
                a[2] = __float_as_uint(odd ? q01 : q00);
                a[3] = __float_as_uint(odd ? q11 : q10);
                int kk = half*64 + ks2*8;
                // paired-V: tokens (qid, qid+4) adjacent at col kk + 2*qid
                #pragma unroll
                for (int dt = 0; dt < 8; dt++) {
                    uint2 vv = *(const uint2*)&Vu[(dt*8+grp)*132 + kk + 2*qid];
                    mma8(ao[dt], a, vv.x, vv.y);
                }
            }
        }
    }
    __syncthreads();

    // PE slab: inverse-permuted scalar reads (slab holds natural token order)
    float* slab = sm;
    const int r0 = m0 >> 5;
    for (int idx = tid; idx < 12288; idx += 256) {
        int t32 = idx & 31;
        int t6 = idx >> 5;
        int srow = t6 % 6, ch = t6 / 6;
        int grow = r0 + srow - 1;
        float v = 0.f;
        if ((unsigned)grow < 32u) {
            int j = t32 & 7;
            int p = (j < 4) ? 2*j : 2*j - 7;
            v = vbase[(size_t)ch*1024 + grow*32 + (t32 & ~7) + p];
        }
        slab[ch*216 + srow*36 + t32] = v;
    }
    __syncthreads();

    float inv0 = 1.f / l_i[0], inv1 = 1.f / l_i[1];
    const int tl0 = wq + grp, tl1 = tl0 + 8;
    const int col0 = tl0 & 31, rl0 = tl0 >> 5;
    const int col1 = tl1 & 31, rl1 = tl1 >> 5;
    float* ob0 = attoT + ((size_t)(b*1024 + m0 + tl0))*256 + h*64;
    float* ob1 = attoT + ((size_t)(b*1024 + m0 + tl1))*256 + h*64;
    #pragma unroll
    for (int dt = 0; dt < 8; dt++) {
        int d0 = dt*8 + 2*qid;
        float pe[2][2];
        #pragma unroll
        for (int e = 0; e < 2; e++) {
            int ch = d0 + e, cg = h*64 + ch;
            const float* wp = pe_w + cg*9;
            float w9[9];
            #pragma unroll
            for (int i = 0; i < 9; i++) w9[i] = wp[i];
            float ss = pe_s[cg], bb2 = pe_b[cg];
            const float* sl = slab + ch*216;
            #pragma unroll
            for (int tk = 0; tk < 2; tk++) {
                int col = tk ? col1 : col0;
                int rl  = tk ? rl1  : rl0;
                float acc2 = 0.f;
                #pragma unroll
                for (int rr = 0; rr < 3; rr++) {
                    const float* q = sl + (rl + rr)*36;
                    #pragma unroll
                    for (int dx = -1; dx <= 1; dx++) {
                        int cx = col + dx;
                        if ((unsigned)cx < 32u) acc2 += q[cx] * w9[rr*3 + dx + 1];
                    }
                }
                pe[e][tk] = acc2 * ss + bb2;
            }
        }
        float2 v0, v1;
        v0.x = ao[dt][0]*inv0 + pe[0][0];
        v0.y = ao[dt][1]*inv0 + pe[1][0];
        v1.x = ao[dt][2]*inv1 + pe[0][1];
        v1.y = ao[dt][3]*inv1 + pe[1][1];
        *(float2*)(ob0 + d0) = v0;
        *(float2*)(ob1 + d0) = v1;
    }
}

// ============ fused dwconv3x3 + GELU-gate + transpose ============
#define DG_SMEM 72192
__global__ void __launch_bounds__(256) dwgate(
    const float* __restrict__ pin, const float* __restrict__ w,
    float* __restrict__ hidT)
{
    extern __shared__ float sm[];
    float* s1 = sm;
    float* s2 = sm + 6912;
    float* t  = sm + 13824;
    const int rg = blockIdx.x, ct = blockIdx.y, b = blockIdx.z;
    const int tid = threadIdx.x;

    for (int idx = tid; idx < 3072; idx += 256) {
        int px4 = idx & 7;
        int rowp = idx >> 3;
        int ch = rowp & 31;
        int rp = rowp >> 5;
        int row = rp % 6, plane = rp / 6;
        int grow = rg*4 + row - 1;
        float4 v = make_float4(0.f, 0.f, 0.f, 0.f);
        if ((unsigned)grow < 32u) {
            const float* gp = pin + ((size_t)b*1024 + ct*32 + ch + plane*512)*1024
                            + grow*32 + px4*4;
            v = *(const float4*)gp;
        }
        float* dst = (plane ? s2 : s1) + ch*216 + row*36 + px4*4;
        *(float4*)dst = v;
    }
    __syncthreads();

    const int wl = tid >> 5, lane = tid & 31;
    #pragma unroll
    for (int cc = 0; cc < 4; cc++) {
        int ch = wl*4 + cc;
        int cg = ct*32 + ch;
        float w1[9], w2[9];
        #pragma unroll
        for (int i = 0; i < 9; i++) { w1[i] = w[cg*9 + i]; w2[i] = w[(cg+512)*9 + i]; }
        const float* p1 = s1 + ch*216;
        const float* p2 = s2 + ch*216;
        #pragma unroll
        for (int r = 0; r < 4; r++) {
            float y1 = 0.f, y2 = 0.f;
            #pragma unroll
            for (int rr = 0; rr < 3; rr++) {
                const float* q1 = p1 + (r+rr)*36;
                const float* q2 = p2 + (r+rr)*36;
                #pragma unroll
                for (int dx = -1; dx <= 1; dx++) {
                    int px = lane + dx;
                    if ((unsigned)px < 32u) {
                        float wa = w1[rr*3 + dx + 1], wb = w2[rr*3 + dx + 1];
                        y1 += q1[px] * wa;
                        y2 += q2[px] * wb;
                    }
                }
            }
            float g = 0.5f * y1 * (1.f + erff(y1 * 0.70710678118654752f));
            t[(r*32 + lane)*33 + ch] = g * y2;
        }
    }
    __syncthreads();

    for (int idx = tid; idx < 1024; idx += 256) {
        int tok = idx >> 3, c4 = (idx & 7) * 4;
        const float* tp = &t[tok*33 + c4];
        float4 v; v.x = tp[0]; v.y = tp[1]; v.z = tp[2]; v.w = tp[3];
        *(float4*)(hidT + ((size_t)b*1024 + rg*128 + tok)*512 + ct*32 + c4) = v;
    }
}

// ============ FFT filter -> circular conv ============
__global__ void fft_g_kernel(const float* __restrict__ filt, float* __restrict__ g)
{
    const float ct[8] = {1.f, 0.70710678118654752f, 0.f, -0.70710678118654752f,
                         -1.f, -0.70710678118654752f, 0.f, 0.70710678118654752f};
    int c = blockIdx.x, t = threadIdx.x;
    int a = t >> 3, bb = t & 7;
    float s = 0.f;
    for (int k1 = 0; k1 < 8; k1++)
        for (int k2 = 0; k2 < 8; k2++) {
            float F = (k2 <= 4) ? filt[c*40 + k1*5 + k2]
                                : filt[c*40 + ((8-k1)&7)*5 + (8-k2)];
            s += F * ct[(k1*a + k2*bb) & 7];
        }
    g[c*64 + t] = s * (1.f/64.f);
}

__global__ void fft_apply_kernel(const float* __restrict__ y, const float* __restrict__ g,
                                 const float* __restrict__ xnew, float* __restrict__ out)
{
    __shared__ float ys[1024];
    __shared__ float gs[64];
    int bc = blockIdx.x, c = bc % 256;
    const float* yp = y + (size_t)bc * 1024;
    int tid = threadIdx.x;
    for (int i = tid; i < 1024; i += 256) ys[i] = yp[i];
    if (tid < 64) gs[tid] = g[c*64 + tid];
    __syncthreads();
    for (int i = tid; i < 1024; i += 256) {
        int u = i >> 5, v = i & 31;
        int bu = u & ~7, bv = v & ~7, uu = u & 7, vv = v & 7;
        float s = 0.f;
        #pragma unroll
        for (int a = 0; a < 8; a++) {
            const float* yr = &ys[(bu + a)*32 + bv];
            const float* gr = &gs[((uu - a) & 7) * 8];
            #pragma unroll
            for (int b2 = 0; b2 < 8; b2++)
                s += gr[(vv - b2) & 7] * yr[b2];
        }
        size_t oi = (size_t)bc * 1024 + i;
        out[oi] = xnew[oi] + s;
    }
}

// =========================================================================
extern "C" void kernel_launch(void* const* d_in, const int* in_sizes, int n_in,
                              void* d_out, int out_size)
{
    const float* x      = (const float*)d_in[0];
    const float* qkv_w  = (const float*)d_in[1];
    const float* qkv_s  = (const float*)d_in[2];
    const float* qkv_b  = (const float*)d_in[3];
    const float* pe_w   = (const float*)d_in[4];
    const float* pe_s   = (const float*)d_in[5];
    const float* pe_b   = (const float*)d_in[6];
    const float* proj_w = (const float*)d_in[7];
    const float* proj_s = (const float*)d_in[8];
    const float* proj_b = (const float*)d_in[9];
    const float* pin_w  = (const float*)d_in[10];
    const float* dw_w   = (const float*)d_in[11];
    const float* ff     = (const float*)d_in[12];
    const float* pout_w = (const float*)d_in[13];
    float* out = (float*)d_out;

    float *qkv, *qkT, *xT, *attoT, *xnew, *xnewT, *pin, *hidT, *yout, *gtab;
    cudaGetSymbolAddress((void**)&qkv,   g_qkv);
    cudaGetSymbolAddress((void**)&qkT,   g_qkT);
    cudaGetSymbolAddress((void**)&xT,    g_xT);
    cudaGetSymbolAddress((void**)&attoT, g_attoT);
    cudaGetSymbolAddress((void**)&xnew,  g_xnew);
    cudaGetSymbolAddress((void**)&xnewT, g_xnewT);
    cudaGetSymbolAddress((void**)&pin,   g_pin);
    cudaGetSymbolAddress((void**)&hidT,  g_hidT);
    cudaGetSymbolAddress((void**)&yout,  g_yout);
    cudaGetSymbolAddress((void**)&gtab,  g_g);

    cudaFuncSetAttribute(flash_kernel, cudaFuncAttributeMaxDynamicSharedMemorySize, FA_SMEM);
    cudaFuncSetAttribute(gemm_mma, cudaFuncAttributeMaxDynamicSharedMemorySize, GEMM_SMEM);
    cudaFuncSetAttribute(dwgate, cudaFuncAttributeMaxDynamicSharedMemorySize, DG_SMEM);
    dim3 tb(32, 8);

    // 0. fft filter table
    fft_g_kernel<<<C_, 64>>>(ff, gtab);
    // 1. xT = transpose(x)
    transpose_kernel<<<dim3(32, 8, 16), tb>>>(x, xT, 262144, 262144, 256, 1024);
    // 2. qkv gemm -> qkv cm (V rows, token-permuted) + qkT token (mode 2)
    gemm_mma<<<dim3(8,4,16), 256, GEMM_SMEM>>>(qkv_w, 256, xT, 256, (size_t)262144,
        qkv, (size_t)524288, 256, qkv_s, qkv_b, nullptr, qkT, 2, 0, 1);
    // 3. flash attention + PE -> attoT token-major
    flash_kernel<<<dim3(8, 64), 256, FA_SMEM>>>(qkT, qkv, pe_w, pe_s, pe_b, attoT);
    // 4. proj gemm -> xnew cm (+x residual) + xnewT token (mode 1)
    gemm_mma<<<dim3(8,2,16), 256, GEMM_SMEM>>>(proj_w, 256, attoT, 256, (size_t)262144,
        xnew, (size_t)262144, 256, proj_s, proj_b, x, xnewT, 1, (size_t)262144, 0);
    // 5. pin gemm -> pin cm
    gemm_mma<<<dim3(8,8,16), 256, GEMM_SMEM>>>(pin_w, 256, xnewT, 256, (size_t)262144,
        pin, (size_t)1048576, 256, nullptr, nullptr, nullptr, nullptr, 0, 0, 0);
    // 6. fused dwconv + gate + transpose -> hidT
    dwgate<<<dim3(8, 16, 16), 256, DG_SMEM>>>(pin, dw_w, hidT);
    // 7. pout gemm -> yout cm
    gemm_mma<<<dim3(8,2,16), 256, GEMM_SMEM>>>(pout_w, 512, hidT, 512, (size_t)524288,
        yout, (size_t)262144, 512, nullptr, nullptr, nullptr, nullptr, 0, 0, 0);
    // 8. fft apply + residual
    fft_apply_kernel<<<NB*C_, 256>>>(yout, gtab, xnew, out);
}

// round 17
// speedup vs baseline: 1.1523x; 1.1523x over previous
#include <cuda_runtime.h>
#include <math.h>
#include <stdint.h>

#define NB 16
#define C_ 256

__device__ float g_qkv  [(size_t)NB*512*1024];
__device__ float g_qkT  [(size_t)64*1024*64];
__device__ float g_xT   [(size_t)NB*1024*256];
__device__ float g_attoT[(size_t)NB*1024*256];
__device__ float g_xnew [(size_t)NB*256*1024];
__device__ float g_xnewT[(size_t)NB*1024*256];
__device__ float g_pin  [(size_t)NB*1024*1024];
__device__ float g_hidT [(size_t)NB*1024*512];
__device__ float g_yout [(size_t)NB*256*1024];
__device__ float g_g    [C_*64];

__device__ __forceinline__ uint32_t smem_u32(const void* p){
    uint32_t a;
    asm("{ .reg .u64 t; cvta.to.shared.u64 t, %1; cvt.u32.u64 %0, t; }" : "=r"(a) : "l"(p));
    return a;
}
__device__ __forceinline__ void cpasync16(uint32_t s, const void* g){
    asm volatile("cp.async.ca.shared.global [%0], [%1], 16;" :: "r"(s), "l"(g));
}
__device__ __forceinline__ float ex2(float x){
    float r; asm("ex2.approx.f32 %0, %1;" : "=f"(r) : "f"(x)); return r;
}
__device__ __forceinline__ void mma8(float* d, const uint32_t* a, uint32_t b0, uint32_t b1){
    asm volatile("mma.sync.aligned.m16n8k8.row.col.f32.tf32.tf32.f32 "
        "{%0,%1,%2,%3}, {%4,%5,%6,%7}, {%8,%9}, {%0,%1,%2,%3};"
        : "+f"(d[0]), "+f"(d[1]), "+f"(d[2]), "+f"(d[3])
        : "r"(a[0]), "r"(a[1]), "r"(a[2]), "r"(a[3]), "r"(b0), "r"(b1));
}

// ============ conv1x1 GEMM (R10), cp.async 2-stage, dual write, cmVOnly ====
#define GEMM_SMEM 73728
__global__ void __launch_bounds__(256, 2) gemm_mma(
    const float* __restrict__ A, int lda,
    const float* __restrict__ B, int ldb, size_t bZs,
    float* __restrict__ O, size_t oZs, int K,
    const float* __restrict__ sc, const float* __restrict__ bi,
    const float* __restrict__ res,
    float* __restrict__ tokO, int tokMode, size_t tZs, int cmVOnly)
{
    extern __shared__ float smem[];
    const int tid = threadIdx.x, wid = tid >> 5, lane = tid & 31;
    const int m0 = blockIdx.y*128, n0 = blockIdx.x*128, z = blockIdx.z;
    const float* Bp = B + (size_t)z * bZs;
    const int wm = (wid & 3) * 32, wn = (wid >> 2) * 64;
    const int grp = lane >> 2, qid = lane & 3;
    const uint32_t sb = smem_u32(smem);

    float acc[2][8][4];
    #pragma unroll
    for (int mt = 0; mt < 2; mt++)
    #pragma unroll
        for (int nt = 0; nt < 8; nt++)
        #pragma unroll
            for (int r = 0; r < 4; r++) acc[mt][nt][r] = 0.f;

    const int nkc = K >> 5;
    auto issue = [&](int i, int st){
        int k0 = i << 5;
        uint32_t abase = sb + st*36864u;
        uint32_t bbase = abase + 18432u;
        #pragma unroll
        for (int idx = tid; idx < 1024; idx += 256) {
            int r = idx >> 3, c4 = (idx & 7) * 4;
            cpasync16(abase + (uint32_t)(r*36 + c4)*4u, A + (size_t)(m0+r)*lda + k0 + c4);
            cpasync16(bbase + (uint32_t)(r*36 + c4)*4u, Bp + (size_t)(n0+r)*ldb + k0 + c4);
        }
        asm volatile("cp.async.commit_group;" ::: "memory");
    };

    issue(0, 0);
    for (int i = 0; i < nkc; i++) {
        if (i + 1 < nkc) { issue(i+1, (i+1)&1); }
        if (i + 1 < nkc) asm volatile("cp.async.wait_group 1;" ::: "memory");
        else             asm volatile("cp.async.wait_group 0;" ::: "memory");
        __syncthreads();
        const uint32_t* As = (const uint32_t*)(smem + (i&1)*9216);
        const uint32_t* Bs = As + 4608;
        #pragma unroll
        for (int ks = 0; ks < 4; ks++) {
            int kk = ks * 8;
            uint32_t a[2][4];
            #pragma unroll
            for (int mt = 0; mt < 2; mt++) {
                int r = wm + mt*16 + grp;
                a[mt][0] = As[r*36 + kk + qid];
                a[mt][1] = As[(r+8)*36 + kk + qid];
                a[mt][2] = As[r*36 + kk + qid + 4];
                a[mt][3] = As[(r+8)*36 + kk + qid + 4];
            }
            #pragma unroll
            for (int nt = 0; nt < 8; nt++) {
                int n = wn + nt*8 + grp;
                uint32_t b0 = Bs[n*36 + kk + qid];
                uint32_t b1 = Bs[n*36 + kk + qid + 4];
                mma8(acc[0][nt], a[0], b0, b1);
                mma8(acc[1][nt], a[1], b0, b1);
            }
        }
        __syncthreads();
    }

    #pragma unroll
    for (int mt = 0; mt < 2; mt++) {
        #pragma unroll
        for (int half = 0; half < 2; half++) {
            int mg = m0 + wm + mt*16 + grp + half*8;
            float s1 = sc ? sc[mg] : 1.f;
            float b1 = sc ? bi[mg] : 0.f;
            const float* rb = res ? res + (size_t)z*oZs + (size_t)mg*1024 + n0 + wn : nullptr;
            #pragma unroll
            for (int nt = 0; nt < 8; nt++) {
                int c = nt*8 + 2*qid;
                float vx = acc[mt][nt][half*2]   * s1 + b1;
                float vy = acc[mt][nt][half*2+1] * s1 + b1;
                if (rb) { float2 rv = *(const float2*)(rb + c); vx += rv.x; vy += rv.y; }
                acc[mt][nt][half*2]   = vx;
                acc[mt][nt][half*2+1] = vy;
            }
        }
    }
    if (!cmVOnly || wm >= 64) {
        #pragma unroll
        for (int mt = 0; mt < 2; mt++) {
            #pragma unroll
            for (int half = 0; half < 2; half++) {
                int mg = m0 + wm + mt*16 + grp + half*8;
                float* ob = O + (size_t)z*oZs + (size_t)mg*1024 + n0 + wn;
                #pragma unroll
                for (int nt = 0; nt < 8; nt++) {
                    int c = nt*8 + 2*qid;
                    float2 v; v.x = acc[mt][nt][half*2]; v.y = acc[mt][nt][half*2+1];
                    *(float2*)(ob + c) = v;
                }
            }
        }
    }
    if (tokMode) {
        const int tS = (tokMode == 2) ? 68 : 132;
        float* Ts = smem;
        for (int nh = 0; nh < 2; nh++) {
            if ((wid >> 2) == nh && (tokMode == 1 || wm < 64)) {
                #pragma unroll
                for (int mt = 0; mt < 2; mt++)
                #pragma unroll
                    for (int hh = 0; hh < 2; hh++) {
                        int ml = wm + mt*16 + grp + hh*8;
                        #pragma unroll
                        for (int nt = 0; nt < 8; nt++) {
                            int r = nt*8 + 2*qid;
                            Ts[r*tS + ml]     = acc[mt][nt][hh*2];
                            Ts[(r+1)*tS + ml] = acc[mt][nt][hh*2+1];
                        }
                    }
            }
            __syncthreads();
            if (tokMode == 1) {
                float* dst = tokO + (size_t)z*tZs + (size_t)(n0 + nh*64)*256 + m0;
                #pragma unroll
                for (int idx = tid; idx < 2048; idx += 256) {
                    int r = idx >> 5, c4 = (idx & 31) * 4;
                    float4 v = *(float4*)&Ts[r*tS + c4];
                    *(float4*)(dst + (size_t)r*256 + c4) = v;
                }
            } else {
                float* dst = tokO + ((size_t)(z*4 + (m0 >> 7))*1024 + n0 + nh*64)*64;
                #pragma unroll
                for (int idx = tid; idx < 1024; idx += 256) {
                    int r = idx >> 4, c4 = (idx & 15) * 4;
                    float4 v = *(float4*)&Ts[r*tS + c4];
                    *(float4*)(dst + r*64 + c4) = v;
                }
            }
            __syncthreads();
        }
    }
}

// ============ 32x32 tiled transpose (input x only) ============
__global__ void transpose_kernel(const float* __restrict__ src, float* __restrict__ dst,
                                 size_t sStr, size_t dStr, int R, int C)
{
    __shared__ float t[32][33];
    const float* s = src + (size_t)blockIdx.z * sStr;
    float* d = dst + (size_t)blockIdx.z * dStr;
    int c0 = blockIdx.x*32, r0 = blockIdx.y*32;
    int tx = threadIdx.x, ty = threadIdx.y;
    #pragma unroll
    for (int k = 0; k < 32; k += 8)
        t[ty+k][tx] = s[(size_t)(r0+ty+k)*C + c0+tx];
    __syncthreads();
    #pragma unroll
    for (int k = 0; k < 32; k += 8)
        d[(size_t)(c0+ty+k)*R + r0+tx] = t[tx][ty+k];
}

// ============ flash v4 (R15): Q in regs, ex2 softmax, scalar V, PE ========
#define FA_SMEM 104448
__global__ void __launch_bounds__(256, 2) flash_kernel(
    const float* __restrict__ qkT, const float* __restrict__ qkv,
    const float* __restrict__ pe_w, const float* __restrict__ pe_s,
    const float* __restrict__ pe_b,
    float* __restrict__ attoT)
{
    extern __shared__ float sm[];
    const int tid = threadIdx.x, wid = tid >> 5, lane = tid & 31;
    const int grp = lane >> 2, qid = lane & 3;
    const int lanebase = lane & ~3, odd = qid & 1;
    const int src1 = lanebase + (qid >> 1), src2 = src1 + 2;
    const int m0 = blockIdx.x * 128, bh = blockIdx.y;
    const int b = bh >> 2, h = bh & 3;
    const int wq = wid * 16;
    const float* qbase = qkT + ((size_t)bh*1024 + m0)*64;
    const float* vbase = qkv + (size_t)b*524288 + (size_t)(h*128+64)*1024;
    const uint32_t sb = smem_u32(sm);
    const uint32_t koff = 4608u*4u, voff = 9216u*4u, vstr = 8448u*4u;
    const float cs2 = 0.17677669529663687f * 1.4426950408889634f;

    {
        const float* kb0 = qkT + ((size_t)bh*1024)*64 + 32;
        #pragma unroll
        for (int idx = tid; idx < 1024; idx += 256) {
            int r = idx >> 3, c4 = (idx & 7) * 4;
            cpasync16(sb + (uint32_t)(r*36 + c4)*4u, qbase + r*64 + c4);
            cpasync16(sb + koff + (uint32_t)(r*36 + c4)*4u, kb0 + r*64 + c4);
        }
        #pragma unroll
        for (int idx = tid; idx < 2048; idx += 256) {
            int dd = idx >> 5, c4 = (idx & 31) * 4;
            cpasync16(sb + voff + (uint32_t)(dd*132 + c4)*4u, vbase + (size_t)dd*1024 + c4);
        }
        asm volatile("cp.async.commit_group;" ::: "memory");
    }

    float m_i[2] = {-1e30f, -1e30f};
    float l_i[2] = {0.f, 0.f};
    float ao[8][4];
    #pragma unroll
    for (int dt = 0; dt < 8; dt++) { ao[dt][0]=0; ao[dt][1]=0; ao[dt][2]=0; ao[dt][3]=0; }

    const uint32_t* Qu = (const uint32_t*)sm;
    const uint32_t* Ku = (const uint32_t*)(sm + 4608);

    // prologue wait; pin Q fragments in registers
    asm volatile("cp.async.wait_group 0;" ::: "memory");
    __syncthreads();
    uint32_t qa[4][4];
    #pragma unroll
    for (int ks = 0; ks < 4; ks++) {
        int kk = ks * 8;
        qa[ks][0] = Qu[(wq+grp)*36 + kk + qid];
        qa[ks][1] = Qu[(wq+grp+8)*36 + kk + qid];
        qa[ks][2] = Qu[(wq+grp)*36 + kk + qid + 4];
        qa[ks][3] = Qu[(wq+grp+8)*36 + kk + qid + 4];
    }

    for (int kc = 0; kc < 8; kc++) {
        if (kc > 0) {   // chunk 0 already resident from prologue
            asm volatile("cp.async.wait_group 0;" ::: "memory");
            __syncthreads();
        }
        const uint32_t* Vu = (const uint32_t*)(sm + 9216 + (kc & 1)*8448);

        #pragma unroll
        for (int half = 0; half < 2; half++) {
            float sacc[8][4];
            #pragma unroll
            for (int nt = 0; nt < 8; nt++) { sacc[nt][0]=0; sacc[nt][1]=0; sacc[nt][2]=0; sacc[nt][3]=0; }
            #pragma unroll
            for (int ks = 0; ks < 4; ks++) {
                int kk = ks * 8;
                #pragma unroll
                for (int nt = 0; nt < 8; nt++) {
                    int n = half*64 + nt*8 + grp;
                    uint32_t b0 = Ku[n*36 + kk + qid];
                    uint32_t b1 = Ku[n*36 + kk + qid + 4];
                    mma8(sacc[nt], qa[ks], b0, b1);
                }
            }
            if (half == 1) {
                __syncthreads();
                if (kc < 7) {
                    const float* kbn = qkT + ((size_t)bh*1024 + (kc+1)*128)*64 + 32;
                    const float* vbn = vbase + (kc+1)*128;
                    uint32_t vdst = sb + voff + (uint32_t)((kc+1)&1)*vstr;
                    #pragma unroll
                    for (int idx = tid; idx < 1024; idx += 256) {
                        int r = idx >> 3, c4 = (idx & 7) * 4;
                        cpasync16(sb + koff + (uint32_t)(r*36 + c4)*4u, kbn + r*64 + c4);
                    }
                    #pragma unroll
                    for (int idx = tid; idx < 2048; idx += 256) {
                        int dd = idx >> 5, c4 = (idx & 31) * 4;
                        cpasync16(vdst + (uint32_t)(dd*132 + c4)*4u, vbn + (size_t)dd*1024 + c4);
                    }
                    asm volatile("cp.async.commit_group;" ::: "memory");
                }
            }
            float mx0 = -1e30f, mx1 = -1e30f;
            #pragma unroll
            for (int nt = 0; nt < 8; nt++) {
                mx0 = fmaxf(mx0, fmaxf(sacc[nt][0], sacc[nt][1]));
                mx1 = fmaxf(mx1, fmaxf(sacc[nt][2], sacc[nt][3]));
            }
            mx0 = fmaxf(mx0, __shfl_xor_sync(0xffffffffu, mx0, 1));
            mx0 = fmaxf(mx0, __shfl_xor_sync(0xffffffffu, mx0, 2));
            mx1 = fmaxf(mx1, __shfl_xor_sync(0xffffffffu, mx1, 1));
            mx1 = fmaxf(mx1, __shfl_xor_sync(0xffffffffu, mx1, 2));
            float mn0 = fmaxf(m_i[0], mx0), mn1 = fmaxf(m_i[1], mx1);
            float mb0 = -mn0 * cs2, mb1 = -mn1 * cs2;
            float s0 = 0.f, s1 = 0.f;
            #pragma unroll
            for (int nt = 0; nt < 8; nt++) {
                sacc[nt][0] = ex2(fmaf(sacc[nt][0], cs2, mb0));
                sacc[nt][1] = ex2(fmaf(sacc[nt][1], cs2, mb0));
                sacc[nt][2] = ex2(fmaf(sacc[nt][2], cs2, mb1));
                sacc[nt][3] = ex2(fmaf(sacc[nt][3], cs2, mb1));
                s0 += sacc[nt][0] + sacc[nt][1];
                s1 += sacc[nt][2] + sacc[nt][3];
            }
            s0 += __shfl_xor_sync(0xffffffffu, s0, 1);
            s0 += __shfl_xor_sync(0xffffffffu, s0, 2);
            s1 += __shfl_xor_sync(0xffffffffu, s1, 1);
            s1 += __shfl_xor_sync(0xffffffffu, s1, 2);
            float al0 = ex2((m_i[0] - mn0) * cs2), al1 = ex2((m_i[1] - mn1) * cs2);
            l_i[0] = l_i[0]*al0 + s0; l_i[1] = l_i[1]*al1 + s1;
            m_i[0] = mn0; m_i[1] = mn1;
            #pragma unroll
            for (int dt = 0; dt < 8; dt++) {
                ao[dt][0] *= al0; ao[dt][1] *= al0;
                ao[dt][2] *= al1; ao[dt][3] *= al1;
            }
            #pragma unroll
            for (int ks2 = 0; ks2 < 8; ks2++) {
                float p00 = __shfl_sync(0xffffffffu, sacc[ks2][0], src1);
                float p01 = __shfl_sync(0xffffffffu, sacc[ks2][1], src1);
                float p10 = __shfl_sync(0xffffffffu, sacc[ks2][2], src1);
                float p11 = __shfl_sync(0xffffffffu, sacc[ks2][3], src1);
                float q00 = __shfl_sync(0xffffffffu, sacc[ks2][0], src2);
                float q01 = __shfl_sync(0xffffffffu, sacc[ks2][1], src2);
                float q10 = __shfl_sync(0xffffffffu, sacc[ks2][2], src2);
                float q11 = __shfl_sync(0xffffffffu, sacc[ks2][3], src2);
                uint32_t a[4];
                a[0] = __float_as_uint(odd ? p01 : p00);
                a[1] = __float_as_uint(odd ? p11 : p10);
                a[2] = __float_as_uint(odd ? q01 : q00);
                a[3] = __float_as_uint(odd ? q11 : q10);
                int kk = half*64 + ks2*8;
                #pragma unroll
                for (int dt = 0; dt < 8; dt++) {
                    uint32_t b0 = Vu[(dt*8+grp)*132 + kk + qid];
                    uint32_t b1 = Vu[(dt*8+grp)*132 + kk + qid + 4];
                    mma8(ao[dt], a, b0, b1);
                }
            }
        }
    }
    __syncthreads();

    float* slab = sm;
    const int r0 = m0 >> 5;
    for (int idx = tid; idx < 3072; idx += 256) {
        int c4 = idx & 7;
        int t6 = idx >> 3;
        int srow = t6 % 6, ch = t6 / 6;
        int grow = r0 + srow - 1;
        float4 v = make_float4(0.f, 0.f, 0.f, 0.f);
        if ((unsigned)grow < 32u)
            v = *(const float4*)(vbase + (size_t)ch*1024 + grow*32 + c4*4);
        *(float4*)(slab + ch*216 + srow*36 + c4*4) = v;
    }
    __syncthreads();

    float inv0 = 1.f / l_i[0], inv1 = 1.f / l_i[1];
    const int tl0 = wq + grp, tl1 = tl0 + 8;
    const int col0 = tl0 & 31, rl0 = tl0 >> 5;
    const int col1 = tl1 & 31, rl1 = tl1 >> 5;
    float* ob0 = attoT + ((size_t)(b*1024 + m0 + tl0))*256 + h*64;
    float* ob1 = attoT + ((size_t)(b*1024 + m0 + tl1))*256 + h*64;
    #pragma unroll
    for (int dt = 0; dt < 8; dt++) {
        int d0 = dt*8 + 2*qid;
        float pe[2][2];
        #pragma unroll
        for (int e = 0; e < 2; e++) {
            int ch = d0 + e, cg = h*64 + ch;
            const float* wp = pe_w + cg*9;
            float w9[9];
            #pragma unroll
            for (int i = 0; i < 9; i++) w9[i] = wp[i];
            float ss = pe_s[cg], bb2 = pe_b[cg];
            const float* sl = slab + ch*216;
            #pragma unroll
            for (int tk = 0; tk < 2; tk++) {
                int col = tk ? col1 : col0;
                int rl  = tk ? rl1  : rl0;
                float acc2 = 0.f;
                #pragma unroll
                for (int rr = 0; rr < 3; rr++) {
                    const float* q = sl + (rl + rr)*36;
                    #pragma unroll
                    for (int dx = -1; dx <= 1; dx++) {
                        int cx = col + dx;
                        if ((unsigned)cx < 32u) acc2 += q[cx] * w9[rr*3 + dx + 1];
                    }
                }
                pe[e][tk] = acc2 * ss + bb2;
            }
        }
        float2 v0, v1;
        v0.x = ao[dt][0]*inv0 + pe[0][0];
        v0.y = ao[dt][1]*inv0 + pe[1][0];
        v1.x = ao[dt][2]*inv1 + pe[0][1];
        v1.y = ao[dt][3]*inv1 + pe[1][1];
        *(float2*)(ob0 + d0) = v0;
        *(float2*)(ob1 + d0) = v1;
    }
}

// ============ fused dwconv3x3 + GELU-gate + transpose ============
#define DG_SMEM 72192
__global__ void __launch_bounds__(256) dwgate(
    const float* __restrict__ pin, const float* __restrict__ w,
    float* __restrict__ hidT)
{
    extern __shared__ float sm[];
    float* s1 = sm;
    float* s2 = sm + 6912;
    float* t  = sm + 13824;
    const int rg = blockIdx.x, ct = blockIdx.y, b = blockIdx.z;
    const int tid = threadIdx.x;

    for (int idx = tid; idx < 3072; idx += 256) {
        int px4 = idx & 7;
        int rowp = idx >> 3;
        int ch = rowp & 31;
        int rp = rowp >> 5;
        int row = rp % 6, plane = rp / 6;
        int grow = rg*4 + row - 1;
        float4 v = make_float4(0.f, 0.f, 0.f, 0.f);
        if ((unsigned)grow < 32u) {
            const float* gp = pin + ((size_t)b*1024 + ct*32 + ch + plane*512)*1024
                            + grow*32 + px4*4;
            v = *(const float4*)gp;
        }
        float* dst = (plane ? s2 : s1) + ch*216 + row*36 + px4*4;
        *(float4*)dst = v;
    }
    __syncthreads();

    const int wl = tid >> 5, lane = tid & 31;
    #pragma unroll
    for (int cc = 0; cc < 4; cc++) {
        int ch = wl*4 + cc;
        int cg = ct*32 + ch;
        float w1[9], w2[9];
        #pragma unroll
        for (int i = 0; i < 9; i++) { w1[i] = w[cg*9 + i]; w2[i] = w[(cg+512)*9 + i]; }
        const float* p1 = s1 + ch*216;
        const float* p2 = s2 + ch*216;
        #pragma unroll
        for (int r = 0; r < 4; r++) {
            float y1 = 0.f, y2 = 0.f;
            #pragma unroll
            for (int rr = 0; rr < 3; rr++) {
                const float* q1 = p1 + (r+rr)*36;
                const float* q2 = p2 + (r+rr)*36;
                #pragma unroll
                for (int dx = -1; dx <= 1; dx++) {
                    int px = lane + dx;
                    if ((unsigned)px < 32u) {
                        float wa = w1[rr*3 + dx + 1], wb = w2[rr*3 + dx + 1];
                        y1 += q1[px] * wa;
                        y2 += q2[px] * wb;
                    }
                }
            }
            float g = 0.5f * y1 * (1.f + erff(y1 * 0.70710678118654752f));
            t[(r*32 + lane)*33 + ch] = g * y2;
        }
    }
    __syncthreads();

    for (int idx = tid; idx < 1024; idx += 256) {
        int tok = idx >> 3, c4 = (idx & 7) * 4;
        const float* tp = &t[tok*33 + c4];
        float4 v; v.x = tp[0]; v.y = tp[1]; v.z = tp[2]; v.w = tp[3];
        *(float4*)(hidT + ((size_t)b*1024 + rg*128 + tok)*512 + ct*32 + c4) = v;
    }
}

// ============ FFT filter -> circular conv ============
__global__ void fft_g_kernel(const float* __restrict__ filt, float* __restrict__ g)
{
    const float ct[8] = {1.f, 0.70710678118654752f, 0.f, -0.70710678118654752f,
                         -1.f, -0.70710678118654752f, 0.f, 0.70710678118654752f};
    int c = blockIdx.x, t = threadIdx.x;
    int a = t >> 3, bb = t & 7;
    float s = 0.f;
    for (int k1 = 0; k1 < 8; k1++)
        for (int k2 = 0; k2 < 8; k2++) {
            float F = (k2 <= 4) ? filt[c*40 + k1*5 + k2]
                                : filt[c*40 + ((8-k1)&7)*5 + (8-k2)];
            s += F * ct[(k1*a + k2*bb) & 7];
        }
    g[c*64 + t] = s * (1.f/64.f);
}

__global__ void fft_apply_kernel(const float* __restrict__ y, const float* __restrict__ g,
                                 const float* __restrict__ xnew, float* __restrict__ out)
{
    __shared__ float ys[1024];
    __shared__ float gs[64];
    int bc = blockIdx.x, c = bc % 256;
    const float* yp = y + (size_t)bc * 1024;
    int tid = threadIdx.x;
    // vectorized tile load
    if (tid < 256) {
        float4 v = *(const float4*)(yp + tid*4);
        *(float4*)(ys + tid*4) = v;
    }
    if (tid < 64) gs[tid] = g[c*64 + tid];
    __syncthreads();
    // each thread computes 4 consecutive outputs (same row), vector add+store
    {
        int i0 = tid * 4;
        int u = i0 >> 5, v4 = i0 & 31;
        int bu = u & ~7, uu = u & 7;
        float o[4];
        #pragma unroll
        for (int j = 0; j < 4; j++) {
            int v = v4 + j;
            int bv = v & ~7, vv = v & 7;
            float s = 0.f;
            #pragma unroll
            for (int a = 0; a < 8; a++) {
                const float* yr = &ys[(bu + a)*32 + bv];
                const float* gr = &gs[((uu - a) & 7) * 8];
                #pragma unroll
                for (int b2 = 0; b2 < 8; b2++)
                    s += gr[(vv - b2) & 7] * yr[b2];
            }
            o[j] = s;
        }
        size_t oi = (size_t)bc * 1024 + i0;
        float4 rv = *(const float4*)(xnew + oi);
        float4 w; w.x = rv.x + o[0]; w.y = rv.y + o[1]; w.z = rv.z + o[2]; w.w = rv.w + o[3];
        *(float4*)(out + oi) = w;
    }
}

// =========================================================================
extern "C" void kernel_launch(void* const* d_in, const int* in_sizes, int n_in,
                              void* d_out, int out_size)
{
    const float* x      = (const float*)d_in[0];
    const float* qkv_w  = (const float*)d_in[1];
    const float* qkv_s  = (const float*)d_in[2];
    const float* qkv_b  = (const float*)d_in[3];
    const float* pe_w   = (const float*)d_in[4];
    const float* pe_s   = (const float*)d_in[5];
    const float* pe_b   = (const float*)d_in[6];
    const float* proj_w = (const float*)d_in[7];
    const float* proj_s = (const float*)d_in[8];
    const float* proj_b = (const float*)d_in[9];
    const float* pin_w  = (const float*)d_in[10];
    const float* dw_w   = (const float*)d_in[11];
    const float* ff     = (const float*)d_in[12];
    const float* pout_w = (const float*)d_in[13];
    float* out = (float*)d_out;

    float *qkv, *qkT, *xT, *attoT, *xnew, *xnewT, *pin, *hidT, *yout, *gtab;
    cudaGetSymbolAddress((void**)&qkv,   g_qkv);
    cudaGetSymbolAddress((void**)&qkT,   g_qkT);
    cudaGetSymbolAddress((void**)&xT,    g_xT);
    cudaGetSymbolAddress((void**)&attoT, g_attoT);
    cudaGetSymbolAddress((void**)&xnew,  g_xnew);
    cudaGetSymbolAddress((void**)&xnewT, g_xnewT);
    cudaGetSymbolAddress((void**)&pin,   g_pin);
    cudaGetSymbolAddress((void**)&hidT,  g_hidT);
    cudaGetSymbolAddress((void**)&yout,  g_yout);
    cudaGetSymbolAddress((void**)&gtab,  g_g);

    cudaFuncSetAttribute(flash_kernel, cudaFuncAttributeMaxDynamicSharedMemorySize, FA_SMEM);
    cudaFuncSetAttribute(gemm_mma, cudaFuncAttributeMaxDynamicSharedMemorySize, GEMM_SMEM);
    cudaFuncSetAttribute(dwgate, cudaFuncAttributeMaxDynamicSharedMemorySize, DG_SMEM);
    dim3 tb(32, 8);

    // 0. fft filter table
    fft_g_kernel<<<C_, 64>>>(ff, gtab);
    // 1. xT = transpose(x)
    transpose_kernel<<<dim3(32, 8, 16), tb>>>(x, xT, 262144, 262144, 256, 1024);
    // 2. qkv gemm -> qkv cm (V rows only) + qkT token (mode 2)
    gemm_mma<<<dim3(8,4,16), 256, GEMM_SMEM>>>(qkv_w, 256, xT, 256, (size_t)262144,
        qkv, (size_t)524288, 256, qkv_s, qkv_b, nullptr, qkT, 2, 0, 1);
    // 3. flash attention + PE -> attoT token-major
    flash_kernel<<<dim3(8, 64), 256, FA_SMEM>>>(qkT, qkv, pe_w, pe_s, pe_b, attoT);
    // 4. proj gemm -> xnew cm (+x residual) + xnewT token (mode 1)
    gemm_mma<<<dim3(8,2,16), 256, GEMM_SMEM>>>(proj_w, 256, attoT, 256, (size_t)262144,
        xnew, (size_t)262144, 256, proj_s, proj_b, x, xnewT, 1, (size_t)262144, 0);
    // 5. pin gemm -> pin cm
    gemm_mma<<<dim3(8,8,16), 256, GEMM_SMEM>>>(pin_w, 256, xnewT, 256, (size_t)262144,
        pin, (size_t)1048576, 256, nullptr, nullptr, nullptr, nullptr, 0, 0, 0);
    // 6. fused dwconv + gate + transpose -> hidT
    dwgate<<<dim3(8, 16, 16), 256, DG_SMEM>>>(pin, dw_w, hidT);
    // 7. pout gemm -> yout cm
    gemm_mma<<<dim3(8,2,16), 256, GEMM_SMEM>>>(pout_w, 512, hidT, 512, (size_t)524288,
        yout, (size_t)262144, 512, nullptr, nullptr, nullptr, nullptr, 0, 0, 0);
    // 8. fft apply + residual
    fft_apply_kernel<<<NB*C_, 256>>>(yout, gtab, xnew, out);
}